// round 2
// baseline (speedup 1.0000x reference)
#include <cuda_runtime.h>
#include <cuda_bf16.h>

#define NBINS 256
#define NCH 3
#define NHIST (NBINS * NCH)   // 768
#define NREP 4                // shared-histogram replicas per block
#define BLOCK_THREADS 256
#define GRID_BLOCKS (148 * 8) // 1184 blocks, ~8 resident CTAs/SM

__device__ unsigned int g_counts[NHIST];

__global__ void zero_counts_kernel() {
    int i = blockIdx.x * blockDim.x + threadIdx.x;
    if (i < NHIST) g_counts[i] = 0u;
}

__device__ __forceinline__ int bin_of(float x) {
    // TF histogram_fixed_width rule: clip(int(x*256), 0, 255), trunc toward zero
    int b = __float2int_rz(x * 256.0f);
    b = max(0, min(255, b));
    return b;
}

__global__ void __launch_bounds__(BLOCK_THREADS)
hist_kernel(const float4* __restrict__ in4, int n4,
            const float* __restrict__ in, int n_total) {
    __shared__ unsigned int sh[NREP][NHIST];

    // Zero shared replicas
    for (int i = threadIdx.x; i < NREP * NHIST; i += blockDim.x)
        ((unsigned int*)sh)[i] = 0u;
    __syncthreads();

    // Each warp uses one replica (round-robin) to reduce same-address serialization
    unsigned int* h = sh[(threadIdx.x >> 5) & (NREP - 1)];

    int stride = gridDim.x * blockDim.x;
    for (int j = blockIdx.x * blockDim.x + threadIdx.x; j < n4; j += stride) {
        float4 v = in4[j];
        // base element index = 4*j; 4 = 1 (mod 3) => base channel = j % 3
        int c0 = j % 3;
        int c1 = c0 + 1; if (c1 >= 3) c1 -= 3;
        int c2 = c1 + 1; if (c2 >= 3) c2 -= 3;
        // 4th element wraps back to c0
        atomicAdd(&h[c0 * NBINS + bin_of(v.x)], 1u);
        atomicAdd(&h[c1 * NBINS + bin_of(v.y)], 1u);
        atomicAdd(&h[c2 * NBINS + bin_of(v.z)], 1u);
        atomicAdd(&h[c0 * NBINS + bin_of(v.w)], 1u);
    }

    // Scalar tail (n_total not divisible by 4) — handled by block 0 only
    if (blockIdx.x == 0) {
        int base = n4 * 4;
        for (int i = base + threadIdx.x; i < n_total; i += blockDim.x) {
            int c = i % 3;
            atomicAdd(&h[c * NBINS + bin_of(in[i])], 1u);
        }
    }

    __syncthreads();

    // Reduce replicas and publish to global counters
    for (int i = threadIdx.x; i < NHIST; i += blockDim.x) {
        unsigned int s = 0u;
        #pragma unroll
        for (int r = 0; r < NREP; r++) s += sh[r][i];
        if (s) atomicAdd(&g_counts[i], s);
    }
}

__global__ void finalize_kernel(float* __restrict__ out, float inv_total) {
    int i = blockIdx.x * blockDim.x + threadIdx.x;
    if (i < NHIST) {
        int c = i / NBINS;
        int b = i - c * NBINS;
        // reference output is hist.T -> shape [nbins, 3], row-major: out[b*3 + c]
        out[b * 3 + c] = (float)g_counts[i] * inv_total;
    }
}

extern "C" void kernel_launch(void* const* d_in, const int* in_sizes, int n_in,
                              void* d_out, int out_size) {
    const float* in = (const float*)d_in[0];
    int n = in_sizes[0];               // 64*512*512*3 = 50,331,648
    int n4 = n / 4;
    int pixels = n / 3;                // per-channel count sum = 16,777,216
    float inv_total = 1.0f / (float)pixels;

    zero_counts_kernel<<<(NHIST + 255) / 256, 256>>>();
    hist_kernel<<<GRID_BLOCKS, BLOCK_THREADS>>>((const float4*)in, n4, in, n);
    finalize_kernel<<<(NHIST + 255) / 256, 256>>>((float*)d_out, inv_total);
}